// round 1
// baseline (speedup 1.0000x reference)
#include <cuda_runtime.h>

#define D_MODEL 1024
#define NHEADS  16
#define HDIM    64
#define BATCH   2
#define SEQ     2048
#define NROWS   (BATCH * SEQ)     // 4096
#define KDIM    D_MODEL

// GEMM tile config
#define BM 128
#define BN 128
#define BK 8
#define TM 8
#define TN 8

// Scratch (device globals: no allocation allowed in kernel_launch)
__device__ float g_Q [NROWS * D_MODEL];
__device__ float g_K [NROWS * D_MODEL];
__device__ float g_AO[NROWS * D_MODEL];

// ---------------------------------------------------------------------------
// C[M,N] = A[M,K] @ W[N,K]^T + bias   (M=4096, N=1024, K=1024)
// 128x128 tile, BK=8, 256 threads, 8x8 per-thread register tile.
// ---------------------------------------------------------------------------
__device__ __forceinline__ void gemm_body(
    const float* __restrict__ A, const float* __restrict__ W,
    const float* __restrict__ bias, float* __restrict__ C,
    float (*As)[BK + 1], float (*Ws)[BN + 4])
{
    const int K = KDIM;
    const int N = D_MODEL;
    const int tid = threadIdx.x;
    const int tx = tid & 15;      // n direction, 16
    const int ty = tid >> 4;      // m direction, 16
    const int m0 = blockIdx.y * BM;
    const int n0 = blockIdx.x * BN;

    float acc[TM][TN];
#pragma unroll
    for (int i = 0; i < TM; i++)
#pragma unroll
        for (int j = 0; j < TN; j++) acc[i][j] = 0.0f;

    for (int k0 = 0; k0 < K; k0 += BK) {
        // Load A tile [BM][BK] (natural layout, +1 pad)
#pragma unroll
        for (int it = 0; it < (BM * BK) / 256; it++) {
            int e = tid + it * 256;
            int m = e >> 3;
            int k = e & 7;
            As[m][k] = A[(m0 + m) * K + k0 + k];
        }
        // Load W tile transposed into Ws[BK][BN+4] (conflict-free stores w/ pad 4)
#pragma unroll
        for (int it = 0; it < (BN * BK) / 256; it++) {
            int e = tid + it * 256;
            int n = e >> 3;
            int k = e & 7;
            Ws[k][n] = W[(n0 + n) * K + k0 + k];
        }
        __syncthreads();

#pragma unroll
        for (int kk = 0; kk < BK; kk++) {
            float a_frag[TM], w_frag[TN];
#pragma unroll
            for (int i = 0; i < TM; i++) a_frag[i] = As[ty * TM + i][kk];
#pragma unroll
            for (int j = 0; j < TN; j++) w_frag[j] = Ws[kk][tx * TN + j];
#pragma unroll
            for (int i = 0; i < TM; i++)
#pragma unroll
                for (int j = 0; j < TN; j++)
                    acc[i][j] += a_frag[i] * w_frag[j];
        }
        __syncthreads();
    }

    // Epilogue: add bias, vectorized stores
    const int nbase = n0 + tx * TN;
    float4 b0 = *(const float4*)&bias[nbase];
    float4 b1 = *(const float4*)&bias[nbase + 4];
#pragma unroll
    for (int i = 0; i < TM; i++) {
        int m = m0 + ty * TM + i;
        float4 v0, v1;
        v0.x = acc[i][0] + b0.x; v0.y = acc[i][1] + b0.y;
        v0.z = acc[i][2] + b0.z; v0.w = acc[i][3] + b0.w;
        v1.x = acc[i][4] + b1.x; v1.y = acc[i][5] + b1.y;
        v1.z = acc[i][6] + b1.z; v1.w = acc[i][7] + b1.w;
        *(float4*)&C[m * N + nbase]     = v0;
        *(float4*)&C[m * N + nbase + 4] = v1;
    }
}

// Fused Q/K projection: blockIdx.z selects {Wq->g_Q, Wk->g_K}
__global__ __launch_bounds__(256)
void qk_gemm_kernel(const float* __restrict__ A,
                    const float* __restrict__ Wq, const float* __restrict__ bq,
                    const float* __restrict__ Wk, const float* __restrict__ bk)
{
    __shared__ float As[BM][BK + 1];
    __shared__ float Ws[BK][BN + 4];
    const float* W    = blockIdx.z ? Wk : Wq;
    const float* bias = blockIdx.z ? bk : bq;
    float* C          = blockIdx.z ? g_K : g_Q;
    gemm_body(A, W, bias, C, As, Ws);
}

// Output projection: d_out = g_AO @ Wo^T + bo
__global__ __launch_bounds__(256)
void out_gemm_kernel(const float* __restrict__ Wo, const float* __restrict__ bo,
                     float* __restrict__ out)
{
    __shared__ float As[BM][BK + 1];
    __shared__ float Ws[BK][BN + 4];
    gemm_body(g_AO, Wo, bo, out, As, Ws);
}

// ---------------------------------------------------------------------------
// Flash attention: grid (B*NH, SEQ/128), 128 threads; thread t owns query row
// q0+t of head h. K/V tiles (64 keys x 64 dims) staged in SMEM; online softmax.
// ---------------------------------------------------------------------------
__global__ __launch_bounds__(128, 2)
void attn_kernel(const float* __restrict__ V /* = H */)
{
    __shared__ float Ks[64][64];
    __shared__ float Vs[64][64];

    const int t  = threadIdx.x;          // 0..127
    const int bh = blockIdx.x;           // 0..31
    const int b  = bh / NHEADS;
    const int h  = bh % NHEADS;
    const int q0 = blockIdx.y * 128;
    const int row = b * SEQ + q0 + t;
    const float scale = 0.125f;          // 1/sqrt(64)

    // Load this thread's query row (pre-scaled)
    float q[HDIM];
    {
        const float4* qp = (const float4*)(g_Q + (size_t)row * D_MODEL + h * HDIM);
#pragma unroll
        for (int i = 0; i < 16; i++) {
            float4 v = qp[i];
            q[4*i+0] = v.x * scale; q[4*i+1] = v.y * scale;
            q[4*i+2] = v.z * scale; q[4*i+3] = v.w * scale;
        }
    }

    float o[HDIM];
#pragma unroll
    for (int i = 0; i < HDIM; i++) o[i] = 0.0f;
    float mmax = -1e30f, l = 0.0f;

    for (int kt = 0; kt < SEQ / 64; kt++) {
        const float4* Kg = (const float4*)(g_K + (size_t)(b * SEQ + kt * 64) * D_MODEL + h * HDIM);
        const float4* Vg = (const float4*)(V   + (size_t)(b * SEQ + kt * 64) * D_MODEL + h * HDIM);
        // 64 rows x 16 float4 = 1024 float4, 128 threads -> 8 each
#pragma unroll
        for (int i = 0; i < 8; i++) {
            int e  = t + i * 128;
            int kr = e >> 4;
            int kc = e & 15;
            ((float4*)Ks)[kr * 16 + kc] = Kg[kr * 256 + kc];   // 256 = D_MODEL/4
            ((float4*)Vs)[kr * 16 + kc] = Vg[kr * 256 + kc];
        }
        __syncthreads();

#pragma unroll 2
        for (int key = 0; key < 64; key++) {
            const float4* kp = (const float4*)&Ks[key][0];
            float s = 0.0f;
#pragma unroll
            for (int i = 0; i < 16; i++) {
                float4 kv = kp[i];
                s += q[4*i+0]*kv.x + q[4*i+1]*kv.y + q[4*i+2]*kv.z + q[4*i+3]*kv.w;
            }
            if (s > mmax) {                 // rare after warm-up
                float c = __expf(mmax - s);
                l *= c;
#pragma unroll
                for (int i = 0; i < HDIM; i++) o[i] *= c;
                mmax = s;
            }
            float p = __expf(s - mmax);
            l += p;
            const float4* vp = (const float4*)&Vs[key][0];
#pragma unroll
            for (int i = 0; i < 16; i++) {
                float4 vv = vp[i];
                o[4*i+0] += p * vv.x; o[4*i+1] += p * vv.y;
                o[4*i+2] += p * vv.z; o[4*i+3] += p * vv.w;
            }
        }
        __syncthreads();
    }

    const float inv = 1.0f / l;
    float4* op = (float4*)(g_AO + (size_t)row * D_MODEL + h * HDIM);
#pragma unroll
    for (int i = 0; i < 16; i++) {
        float4 v;
        v.x = o[4*i+0] * inv; v.y = o[4*i+1] * inv;
        v.z = o[4*i+2] * inv; v.w = o[4*i+3] * inv;
        op[i] = v;
    }
}

// ---------------------------------------------------------------------------
extern "C" void kernel_launch(void* const* d_in, const int* in_sizes, int n_in,
                              void* d_out, int out_size)
{
    (void)in_sizes; (void)n_in; (void)out_size;
    const float* H  = (const float*)d_in[0];
    const float* Wq = (const float*)d_in[1];
    const float* bq = (const float*)d_in[2];
    const float* Wk = (const float*)d_in[3];
    const float* bk = (const float*)d_in[4];
    const float* Wo = (const float*)d_in[5];
    const float* bo = (const float*)d_in[6];
    float* out = (float*)d_out;

    dim3 gblk(256);
    dim3 qkgrid(D_MODEL / BN, NROWS / BM, 2);   // (8, 32, 2)
    qk_gemm_kernel<<<qkgrid, gblk>>>(H, Wq, bq, Wk, bk);

    dim3 agrid(BATCH * NHEADS, SEQ / 128);      // (32, 16)
    attn_kernel<<<agrid, 128>>>(H);

    dim3 ogrid(D_MODEL / BN, NROWS / BM, 1);    // (8, 32)
    out_gemm_kernel<<<ogrid, gblk>>>(Wo, bo, out);
}